// round 5
// baseline (speedup 1.0000x reference)
#include <cuda_runtime.h>
#include <math.h>

#define H 1024
#define V 50000
#define MAXLEN 35
#define NB 148
#define NT 1024
#define NWARP (NT / 32)        // 32 warps per block
#define GWARPS (NB * NWARP)    // 4736 warps total

// -------- device scratch (no allocations allowed) --------
__device__ float g_u[2 * H];       // [embedded ; attn_applied]
__device__ float g_hg[3 * H];      // W_hh @ h + b_hh
__device__ float g_comb[H];        // relu(W_comb @ u + b_comb)
__device__ float g_hnew[H];        // updated hidden state
__device__ float g_logits[V];      // pre-softmax logits
__device__ float g_bm[NB];         // per-block online max
__device__ float g_bs[NB];         // per-block online scaled sum
__device__ float g_red[1];         // M + log(S)
__device__ unsigned g_count[8];    // barrier arrive counters (self-resetting)
__device__ unsigned g_gen[8];      // barrier generations (monotonic across replays)

__device__ __forceinline__ float warp_sum(float v) {
    #pragma unroll
    for (int o = 16; o > 0; o >>= 1) v += __shfl_down_sync(0xffffffffu, v, o);
    return v;
}

// Grid-wide barrier (all NB CTAs guaranteed resident: 1 CTA/SM by launch_bounds).
__device__ __forceinline__ void gsync(int p) {
    __threadfence();
    __syncthreads();
    if (threadIdx.x == 0) {
        volatile unsigned* genp = &g_gen[p];
        unsigned gen = *genp;
        unsigned old = atomicAdd(&g_count[p], 1u);
        if (old == NB - 1) {
            g_count[p] = 0;
            __threadfence();
            atomicAdd(&g_gen[p], 1u);
        } else {
            while (*genp == gen) { __nanosleep(64); }
        }
    }
    __syncthreads();
}

__global__ void __launch_bounds__(NT, 1)
fused_decoder(const int* __restrict__ x, const float* __restrict__ h,
              const float* __restrict__ enc, const float* __restrict__ emb,
              const float* __restrict__ Wa, const float* __restrict__ ba,
              const float* __restrict__ Wc, const float* __restrict__ bc,
              const float* __restrict__ Wih, const float* __restrict__ bih,
              const float* __restrict__ Whh, const float* __restrict__ bhh,
              const float* __restrict__ Wo, const float* __restrict__ bo,
              float* __restrict__ out) {
    __shared__ float sbuf[2 * H];
    __shared__ float s_w[64];
    __shared__ float s_m[NWARP], s_s[NWARP];

    const int tid = threadIdx.x;
    const int wid = tid >> 5;
    const int lane = tid & 31;
    const int b = blockIdx.x;

    // ===== P0: block 0 -> embedding + attention;  blocks 1..147 -> hg = W_hh@h + b_hh
    if (b == 0) {
        const long row = (long)x[0];
        for (int i = tid; i < H; i += NT) {
            float e = emb[row * H + i];
            sbuf[i] = e;
            g_u[i]  = e;
        }
        for (int i = tid; i < H; i += NT) sbuf[H + i] = h[i];
        __syncthreads();

        for (int m = wid; m < MAXLEN; m += NWARP) {
            const float* Wr = Wa + (long)m * (2 * H);
            float acc = 0.f;
            for (int k = lane; k < 2 * H; k += 32) acc += __ldcs(Wr + k) * sbuf[k];
            acc = warp_sum(acc);
            if (lane == 0) s_w[m] = acc + ba[m];
        }
        __syncthreads();

        if (tid == 0) {
            float mx = -1e30f;
            for (int m = 0; m < MAXLEN; m++) mx = fmaxf(mx, s_w[m]);
            float s = 0.f;
            for (int m = 0; m < MAXLEN; m++) { float e = expf(s_w[m] - mx); s_w[m] = e; s += e; }
            float inv = 1.f / s;
            for (int m = 0; m < MAXLEN; m++) s_w[m] *= inv;
        }
        __syncthreads();

        if (tid < MAXLEN) out[V + H + tid] = s_w[tid];

        for (int i = tid; i < H; i += NT) {
            float acc = 0.f;
            #pragma unroll
            for (int m = 0; m < MAXLEN; m++) acc += s_w[m] * enc[m * H + i];
            g_u[H + i] = acc;
        }
    } else {
        const int gw = (b - 1) * NWARP + wid;           // 0..4703
        const float4* hv = reinterpret_cast<const float4*>(h);
        if (gw < 3 * H) {
            const int r = gw;
            const float4* Wr = reinterpret_cast<const float4*>(Whh + (long)r * H);
            float acc = 0.f;
            #pragma unroll 8
            for (int c = lane; c < H / 4; c += 32) {
                float4 w = __ldcs(Wr + c); float4 v = hv[c];
                acc += w.x * v.x + w.y * v.y + w.z * v.z + w.w * v.w;
            }
            acc = warp_sum(acc);
            if (lane == 0) g_hg[r] = acc + bhh[r];
        }
    }
    gsync(0);

    // ===== P1: comb = relu(W_comb @ u + b_comb)
    for (int i = tid; i < 2 * H; i += NT) sbuf[i] = g_u[i];
    __syncthreads();
    {
        const int r = b + NB * wid;                      // unique; only r < H active
        if (r < H) {
            const float4* Wr = reinterpret_cast<const float4*>(Wc + (long)r * (2 * H));
            const float4* uv = reinterpret_cast<const float4*>(sbuf);
            float acc = 0.f;
            #pragma unroll 8
            for (int c = lane; c < (2 * H) / 4; c += 32) {
                float4 w = __ldcs(Wr + c); float4 v = uv[c];
                acc += w.x * v.x + w.y * v.y + w.z * v.z + w.w * v.w;
            }
            acc = warp_sum(acc);
            if (lane == 0) g_comb[r] = fmaxf(acc + bc[r], 0.f);
        }
    }
    gsync(1);

    // ===== P2: GRU gates + elementwise update fused; warp owns one j
    __syncthreads();
    for (int i = tid; i < H; i += NT) sbuf[i] = g_comb[i];
    __syncthreads();
    {
        const int j = b + NB * wid;
        if (j < H) {
            const float4* W0 = reinterpret_cast<const float4*>(Wih + (long)j * H);
            const float4* W1 = reinterpret_cast<const float4*>(Wih + (long)(H + j) * H);
            const float4* W2 = reinterpret_cast<const float4*>(Wih + (long)(2 * H + j) * H);
            const float4* cv = reinterpret_cast<const float4*>(sbuf);
            float a0 = 0.f, a1 = 0.f, a2 = 0.f;
            #pragma unroll 4
            for (int c = lane; c < H / 4; c += 32) {
                float4 v = cv[c];
                float4 w0 = __ldcs(W0 + c), w1 = __ldcs(W1 + c), w2 = __ldcs(W2 + c);
                a0 += w0.x * v.x + w0.y * v.y + w0.z * v.z + w0.w * v.w;
                a1 += w1.x * v.x + w1.y * v.y + w1.z * v.z + w1.w * v.w;
                a2 += w2.x * v.x + w2.y * v.y + w2.z * v.z + w2.w * v.w;
            }
            a0 = warp_sum(a0); a1 = warp_sum(a1); a2 = warp_sum(a2);
            if (lane == 0) {
                float xr = a0 + bih[j];
                float xz = a1 + bih[H + j];
                float xn = a2 + bih[2 * H + j];
                float rr = 1.f / (1.f + expf(-(xr + g_hg[j])));
                float zz = 1.f / (1.f + expf(-(xz + g_hg[H + j])));
                float nn = tanhf(xn + rr * g_hg[2 * H + j]);
                float hv = (1.f - zz) * nn + zz * h[j];
                g_hnew[j] = hv;
                out[V + j] = hv;
            }
        }
    }
    gsync(2);

    // ===== P3: logits = W_out @ hnew + b_out; 2 rows per warp iter; online logsumexp
    __syncthreads();
    for (int i = tid; i < H; i += NT) sbuf[i] = g_hnew[i];
    __syncthreads();
    {
        const int gw = b * NWARP + wid;                  // 0..4735
        const float4* hv = reinterpret_cast<const float4*>(sbuf);
        float mx = -1e30f, sm = 0.f;                     // lane-0 online state
        for (long r = (long)gw * 2; r < V; r += 2L * GWARPS) {
            const bool two = (r + 1 < V);
            const float4* W0 = reinterpret_cast<const float4*>(Wo + r * H);
            const float4* W1 = reinterpret_cast<const float4*>(Wo + (r + (two ? 1 : 0)) * H);
            float a0 = 0.f, a1 = 0.f;
            #pragma unroll 4
            for (int c = lane; c < H / 4; c += 32) {
                float4 v  = hv[c];
                float4 w0 = __ldcs(W0 + c);
                float4 w1 = __ldcs(W1 + c);
                a0 += w0.x * v.x + w0.y * v.y + w0.z * v.z + w0.w * v.w;
                a1 += w1.x * v.x + w1.y * v.y + w1.z * v.z + w1.w * v.w;
            }
            a0 = warp_sum(a0);
            a1 = warp_sum(a1);
            if (lane == 0) {
                float lg0 = a0 + bo[r];
                g_logits[r] = lg0;
                float nm = fmaxf(mx, lg0);
                sm = sm * expf(mx - nm) + expf(lg0 - nm);
                mx = nm;
                if (two) {
                    float lg1 = a1 + bo[r + 1];
                    g_logits[r + 1] = lg1;
                    nm = fmaxf(mx, lg1);
                    sm = sm * expf(mx - nm) + expf(lg1 - nm);
                    mx = nm;
                }
            }
        }
        if (lane == 0) { s_m[wid] = mx; s_s[wid] = sm; }
        __syncthreads();
        if (tid == 0) {
            float M = -1e30f, S = 0.f;
            #pragma unroll
            for (int w = 0; w < NWARP; w++) {
                float m2 = s_m[w], s2 = s_s[w];
                float nm = fmaxf(M, m2);
                S = S * expf(M - nm) + s2 * expf(m2 - nm);
                M = nm;
            }
            g_bm[b] = M; g_bs[b] = S;
        }
    }
    gsync(3);

    // ===== P4: block 0 warp 0 reduces 148 (m,s) pairs
    if (b == 0 && wid == 0) {
        float M = -1e30f, S = 0.f;
        for (int i = lane; i < NB; i += 32) {
            float m2 = g_bm[i], s2 = g_bs[i];
            float nm = fmaxf(M, m2);
            S = S * expf(M - nm) + s2 * expf(m2 - nm);
            M = nm;
        }
        #pragma unroll
        for (int o = 16; o > 0; o >>= 1) {
            float m2 = __shfl_down_sync(0xffffffffu, M, o);
            float s2 = __shfl_down_sync(0xffffffffu, S, o);
            float nm = fmaxf(M, m2);
            S = S * expf(M - nm) + s2 * expf(m2 - nm);
            M = nm;
        }
        if (lane == 0) g_red[0] = M + logf(S);
    }
    gsync(4);

    // ===== P5: logp = logits - (M + log S)
    {
        const float off = g_red[0];
        for (int v = b * NT + tid; v < V; v += NB * NT) out[v] = g_logits[v] - off;
    }
}

extern "C" void kernel_launch(void* const* d_in, const int* in_sizes, int n_in,
                              void* d_out, int out_size) {
    const int*   x   = (const int*)  d_in[0];
    const float* h   = (const float*)d_in[1];
    const float* enc = (const float*)d_in[3];
    const float* emb = (const float*)d_in[4];
    const float* Wa  = (const float*)d_in[5];
    const float* ba  = (const float*)d_in[6];
    const float* Wc  = (const float*)d_in[7];
    const float* bc  = (const float*)d_in[8];
    const float* Wih = (const float*)d_in[9];
    const float* bih = (const float*)d_in[10];
    const float* Whh = (const float*)d_in[11];
    const float* bhh = (const float*)d_in[12];
    const float* Wo  = (const float*)d_in[13];
    const float* bo  = (const float*)d_in[14];
    float* out = (float*)d_out;

    fused_decoder<<<NB, NT>>>(x, h, enc, emb, Wa, ba, Wc, bc,
                              Wih, bih, Whh, bhh, Wo, bo, out);
}

// round 6
// speedup vs baseline: 1.1194x; 1.1194x over previous
#include <cuda_runtime.h>
#include <math.h>

#define H 1024
#define V 50000
#define MAXLEN 35
#define NB 148
#define NT 512
#define NWARP (NT / 32)        // 16 warps per block
#define GWARPS (NB * NWARP)    // 2368 warps total

// -------- device scratch (no allocations allowed) --------
__device__ float g_u[2 * H];       // [embedded ; attn_applied]
__device__ float g_hg[3 * H];      // W_hh @ h + b_hh
__device__ float g_comb[H];        // relu(W_comb @ u + b_comb)
__device__ float g_hnew[H];        // updated hidden state
__device__ float g_logits[V];      // pre-softmax logits
__device__ float g_bm[NB];         // per-block online max
__device__ float g_bs[NB];         // per-block online scaled sum
__device__ float g_red[1];         // M + log(S)
__device__ unsigned g_count[8];    // barrier arrive counters (self-resetting)
__device__ unsigned g_gen[8];      // barrier generations (monotonic across replays)

__device__ __forceinline__ float warp_sum(float v) {
    #pragma unroll
    for (int o = 16; o > 0; o >>= 1) v += __shfl_down_sync(0xffffffffu, v, o);
    return v;
}

// Grid-wide barrier (all NB CTAs resident: 1 CTA/SM).
__device__ __forceinline__ void gsync(int p) {
    __threadfence();
    __syncthreads();
    if (threadIdx.x == 0) {
        volatile unsigned* genp = &g_gen[p];
        unsigned gen = *genp;
        unsigned old = atomicAdd(&g_count[p], 1u);
        if (old == NB - 1) {
            g_count[p] = 0;
            __threadfence();
            atomicAdd(&g_gen[p], 1u);
        } else {
            while (*genp == gen) { __nanosleep(64); }
        }
    }
    __syncthreads();
}

__global__ void __launch_bounds__(NT, 1)
fused_decoder(const int* __restrict__ x, const float* __restrict__ h,
              const float* __restrict__ enc, const float* __restrict__ emb,
              const float* __restrict__ Wa, const float* __restrict__ ba,
              const float* __restrict__ Wc, const float* __restrict__ bc,
              const float* __restrict__ Wih, const float* __restrict__ bih,
              const float* __restrict__ Whh, const float* __restrict__ bhh,
              const float* __restrict__ Wo, const float* __restrict__ bo,
              float* __restrict__ out) {
    __shared__ float sbuf[2 * H];
    __shared__ float s_w[64];
    __shared__ float s_m[NWARP], s_s[NWARP];

    const int tid = threadIdx.x;
    const int wid = tid >> 5;
    const int lane = tid & 31;
    const int b = blockIdx.x;

    // ===== P0: block 0 -> embedding + attention;  blocks 1..147 -> hg = W_hh@h + b_hh
    if (b == 0) {
        const long row = (long)x[0];
        for (int i = tid; i < H; i += NT) {
            float e = emb[row * H + i];
            sbuf[i] = e;
            g_u[i]  = e;
        }
        for (int i = tid; i < H; i += NT) sbuf[H + i] = h[i];
        __syncthreads();

        for (int m = wid; m < MAXLEN; m += NWARP) {
            const float* Wr = Wa + (long)m * (2 * H);
            float acc = 0.f;
            for (int k = lane; k < 2 * H; k += 32) acc += __ldcs(Wr + k) * sbuf[k];
            acc = warp_sum(acc);
            if (lane == 0) s_w[m] = acc + ba[m];
        }
        __syncthreads();

        if (tid == 0) {
            float mx = -1e30f;
            for (int m = 0; m < MAXLEN; m++) mx = fmaxf(mx, s_w[m]);
            float s = 0.f;
            for (int m = 0; m < MAXLEN; m++) { float e = expf(s_w[m] - mx); s_w[m] = e; s += e; }
            float inv = 1.f / s;
            for (int m = 0; m < MAXLEN; m++) s_w[m] *= inv;
        }
        __syncthreads();

        if (tid < MAXLEN) out[V + H + tid] = s_w[tid];

        for (int i = tid; i < H; i += NT) {
            float acc = 0.f;
            #pragma unroll
            for (int m = 0; m < MAXLEN; m++) acc += s_w[m] * enc[m * H + i];
            g_u[H + i] = acc;
        }
    } else {
        const int gw = (b - 1) * NWARP + wid;           // 0..2351
        const float4* hv = reinterpret_cast<const float4*>(h);
        for (int r = gw; r < 3 * H; r += (NB - 1) * NWARP) {
            const float4* Wr = reinterpret_cast<const float4*>(Whh + (long)r * H);
            float acc = 0.f;
            #pragma unroll 8
            for (int c = lane; c < H / 4; c += 32) {
                float4 w = __ldcs(Wr + c); float4 v = hv[c];
                acc += w.x * v.x + w.y * v.y + w.z * v.z + w.w * v.w;
            }
            acc = warp_sum(acc);
            if (lane == 0) g_hg[r] = acc + bhh[r];
        }
    }
    gsync(0);

    // ===== P1: comb = relu(W_comb @ u + b_comb)
    for (int i = tid; i < 2 * H; i += NT) sbuf[i] = g_u[i];
    __syncthreads();
    {
        const int r = b + NB * wid;                      // unique in 0..2367
        if (r < H) {
            const float4* Wr = reinterpret_cast<const float4*>(Wc + (long)r * (2 * H));
            const float4* uv = reinterpret_cast<const float4*>(sbuf);
            float acc = 0.f;
            #pragma unroll 8
            for (int c = lane; c < (2 * H) / 4; c += 32) {
                float4 w = __ldcs(Wr + c); float4 v = uv[c];
                acc += w.x * v.x + w.y * v.y + w.z * v.z + w.w * v.w;
            }
            acc = warp_sum(acc);
            if (lane == 0) g_comb[r] = fmaxf(acc + bc[r], 0.f);
        }
    }
    gsync(1);

    // ===== P2: GRU gates + elementwise update fused; warp owns one j
    __syncthreads();
    for (int i = tid; i < H; i += NT) sbuf[i] = g_comb[i];
    __syncthreads();
    {
        const int j = b + NB * wid;
        if (j < H) {
            const float4* W0 = reinterpret_cast<const float4*>(Wih + (long)j * H);
            const float4* W1 = reinterpret_cast<const float4*>(Wih + (long)(H + j) * H);
            const float4* W2 = reinterpret_cast<const float4*>(Wih + (long)(2 * H + j) * H);
            const float4* cv = reinterpret_cast<const float4*>(sbuf);
            float a0 = 0.f, a1 = 0.f, a2 = 0.f;
            #pragma unroll 4
            for (int c = lane; c < H / 4; c += 32) {
                float4 v = cv[c];
                float4 w0 = __ldcs(W0 + c), w1 = __ldcs(W1 + c), w2 = __ldcs(W2 + c);
                a0 += w0.x * v.x + w0.y * v.y + w0.z * v.z + w0.w * v.w;
                a1 += w1.x * v.x + w1.y * v.y + w1.z * v.z + w1.w * v.w;
                a2 += w2.x * v.x + w2.y * v.y + w2.z * v.z + w2.w * v.w;
            }
            a0 = warp_sum(a0); a1 = warp_sum(a1); a2 = warp_sum(a2);
            if (lane == 0) {
                float xr = a0 + bih[j];
                float xz = a1 + bih[H + j];
                float xn = a2 + bih[2 * H + j];
                float rr = 1.f / (1.f + expf(-(xr + g_hg[j])));
                float zz = 1.f / (1.f + expf(-(xz + g_hg[H + j])));
                float nn = tanhf(xn + rr * g_hg[2 * H + j]);
                float hv = (1.f - zz) * nn + zz * h[j];
                g_hnew[j] = hv;
                out[V + j] = hv;
            }
        }
    }
    gsync(2);

    // ===== P3: logits = W_out @ hnew + b_out; h_new held in registers;
    //          2 rows / warp iteration; online logsumexp on lane 0.
    {
        const float4* h4 = reinterpret_cast<const float4*>(g_hnew);
        float4 hr[8];
        #pragma unroll
        for (int i = 0; i < 8; i++) hr[i] = h4[lane + 32 * i];

        const int gw = b * NWARP + wid;                  // 0..2367
        float mx = -1e30f, sm = 0.f;
        // V is even and r starts even -> r+1 always valid
        for (int r = gw * 2; r < V; r += 2 * GWARPS) {
            float b0 = 0.f, b1 = 0.f;
            if (lane == 0) { b0 = bo[r]; b1 = bo[r + 1]; }   // prefetch, overlaps loop
            const float4* W0 = reinterpret_cast<const float4*>(Wo + (long)r * H);
            const float4* W1 = reinterpret_cast<const float4*>(Wo + (long)(r + 1) * H);
            float a0 = 0.f, a1 = 0.f;
            #pragma unroll
            for (int i = 0; i < 8; i++) {
                float4 w0 = __ldcs(W0 + lane + 32 * i);
                float4 w1 = __ldcs(W1 + lane + 32 * i);
                a0 += w0.x * hr[i].x + w0.y * hr[i].y + w0.z * hr[i].z + w0.w * hr[i].w;
                a1 += w1.x * hr[i].x + w1.y * hr[i].y + w1.z * hr[i].z + w1.w * hr[i].w;
            }
            a0 = warp_sum(a0);
            a1 = warp_sum(a1);
            if (lane == 0) {
                float lg0 = a0 + b0;
                float lg1 = a1 + b1;
                g_logits[r]     = lg0;
                g_logits[r + 1] = lg1;
                float nm = fmaxf(mx, fmaxf(lg0, lg1));
                sm = sm * expf(mx - nm) + expf(lg0 - nm) + expf(lg1 - nm);
                mx = nm;
            }
        }
        if (lane == 0) { s_m[wid] = mx; s_s[wid] = sm; }
        __syncthreads();
        if (tid == 0) {
            float M = -1e30f, S = 0.f;
            #pragma unroll
            for (int w = 0; w < NWARP; w++) {
                float m2 = s_m[w], s2 = s_s[w];
                float nm = fmaxf(M, m2);
                S = S * expf(M - nm) + s2 * expf(m2 - nm);
                M = nm;
            }
            g_bm[b] = M; g_bs[b] = S;
        }
    }
    gsync(3);

    // ===== P4: block 0 warp 0 reduces 148 (m,s) pairs
    if (b == 0 && wid == 0) {
        float M = -1e30f, S = 0.f;
        for (int i = lane; i < NB; i += 32) {
            float m2 = g_bm[i], s2 = g_bs[i];
            float nm = fmaxf(M, m2);
            S = S * expf(M - nm) + s2 * expf(m2 - nm);
            M = nm;
        }
        #pragma unroll
        for (int o = 16; o > 0; o >>= 1) {
            float m2 = __shfl_down_sync(0xffffffffu, M, o);
            float s2 = __shfl_down_sync(0xffffffffu, S, o);
            float nm = fmaxf(M, m2);
            S = S * expf(M - nm) + s2 * expf(m2 - nm);
            M = nm;
        }
        if (lane == 0) g_red[0] = M + logf(S);
    }
    gsync(4);

    // ===== P5: logp = logits - (M + log S)
    {
        const float off = g_red[0];
        for (int v = b * NT + tid; v < V; v += NB * NT) out[v] = g_logits[v] - off;
    }
}

extern "C" void kernel_launch(void* const* d_in, const int* in_sizes, int n_in,
                              void* d_out, int out_size) {
    const int*   x   = (const int*)  d_in[0];
    const float* h   = (const float*)d_in[1];
    const float* enc = (const float*)d_in[3];
    const float* emb = (const float*)d_in[4];
    const float* Wa  = (const float*)d_in[5];
    const float* ba  = (const float*)d_in[6];
    const float* Wc  = (const float*)d_in[7];
    const float* bc  = (const float*)d_in[8];
    const float* Wih = (const float*)d_in[9];
    const float* bih = (const float*)d_in[10];
    const float* Whh = (const float*)d_in[11];
    const float* bhh = (const float*)d_in[12];
    const float* Wo  = (const float*)d_in[13];
    const float* bo  = (const float*)d_in[14];
    float* out = (float*)d_out;

    fused_decoder<<<NB, NT>>>(x, h, enc, emb, Wa, ba, Wc, bc,
                              Wih, bih, Whh, bhh, Wo, bo, out);
}